// round 6
// baseline (speedup 1.0000x reference)
#include <cuda_runtime.h>
#include <cstdint>
#include <cstddef>

#define DI __device__ __forceinline__
static const int D_DIM = 512;
#define MAXN 32768
#define MAXK 1024
#define NBN  8

extern "C" __device__ float __nv_logf(float);

// Scratch (device globals; no allocation allowed)
__device__ float g_xT[(size_t)D_DIM * MAXN];   // 64MB transposed combined input [d][m]
__device__ float g_cT[(size_t)D_DIM * MAXK];   //  2MB transposed normalized codebook [d][k]
__device__ float g_pm[(size_t)MAXN * NBN];
__device__ int   g_pi[(size_t)MAXN * NBN];
__device__ float g_ps[(size_t)MAXN * NBN];

// ---------------------------------------------------------------------------
// Threefry-2x32 (exact JAX, partitionable mode)
// ---------------------------------------------------------------------------
__host__ __device__ inline uint32_t rotl32(uint32_t x, int r) {
    return (x << r) | (x >> (32 - r));
}
__host__ __device__ inline void threefry2x32(uint32_t k0, uint32_t k1,
                                             uint32_t& x0, uint32_t& x1) {
    uint32_t k2 = k0 ^ k1 ^ 0x1BD11BDAu;
    x0 += k0; x1 += k1;
#define TFR(r) { x0 += x1; x1 = rotl32(x1, r); x1 ^= x0; }
    TFR(13) TFR(15) TFR(26) TFR(6)
    x0 += k1; x1 += k2 + 1u;
    TFR(17) TFR(29) TFR(16) TFR(24)
    x0 += k2; x1 += k0 + 2u;
    TFR(13) TFR(15) TFR(26) TFR(6)
    x0 += k0; x1 += k1 + 3u;
    TFR(17) TFR(29) TFR(16) TFR(24)
    x0 += k1; x1 += k2 + 4u;
    TFR(13) TFR(15) TFR(26) TFR(6)
    x0 += k2; x1 += k0 + 5u;
#undef TFR
}
DI uint32_t tf_bits(uint32_t k0, uint32_t k1, uint32_t i) {
    uint32_t x0 = 0u, x1 = i;
    threefry2x32(k0, k1, x0, x1);
    return x0 ^ x1;
}
#define TINYF 1.17549435e-38f

// ---------------------------------------------------------------------------
// Packed fp32x2 FMA helpers
// ---------------------------------------------------------------------------
typedef unsigned long long u64;
DI u64 pk2(float lo, float hi) {
    u64 r; asm("mov.b64 %0, {%1,%2};" : "=l"(r) : "f"(lo), "f"(hi)); return r;
}
DI void upk2(u64 p, float& lo, float& hi) {
    asm("mov.b64 {%0,%1}, %2;" : "=f"(lo), "=f"(hi) : "l"(p));
}
DI u64 fma2(u64 a, u64 b, u64 c) {
    u64 d; asm("fma.rn.f32x2 %0, %1, %2, %3;" : "=l"(d) : "l"(a), "l"(b), "l"(c));
    return d;
}
DI uint32_t smem_u32(const void* p) {
    uint32_t a;
    asm("{ .reg .u64 t; cvta.to.shared.u64 t, %1; cvt.u32.u64 %0, t; }"
        : "=r"(a) : "l"(p));
    return a;
}
DI void cp16(uint32_t saddr, const void* g) {
    asm volatile("cp.async.cg.shared.global [%0], [%1], 16;"
                 :: "r"(saddr), "l"(g) : "memory");
}
#define CP_COMMIT() asm volatile("cp.async.commit_group;" ::: "memory")
#define CP_WAIT1()  asm volatile("cp.async.wait_group 1;" ::: "memory")
#define CP_WAIT0()  asm volatile("cp.async.wait_group 0;" ::: "memory")
DI void lds128(float* r, uint32_t addr) {
    asm volatile("ld.shared.v4.f32 {%0,%1,%2,%3}, [%4];"
        : "=f"(r[0]), "=f"(r[1]), "=f"(r[2]), "=f"(r[3]) : "r"(addr));
}

// ---------------------------------------------------------------------------
// Kernel 1: codebook: normalize rows, write TRANSPOSED g_cT[d][k]
// ---------------------------------------------------------------------------
__global__ __launch_bounds__(256) void norm_cb_T(const float* __restrict__ cb) {
    __shared__ float sx[16][529];
    int t = threadIdx.x, lane = t & 31, w = t >> 5;
    int k0 = blockIdx.x * 16;
#pragma unroll
    for (int rr = 0; rr < 2; rr++) {
        int row = w * 2 + rr;
        const float4* rp = (const float4*)(cb + (size_t)(k0 + row) * D_DIM);
        float4 v[4]; float ss = 0.f;
#pragma unroll
        for (int i = 0; i < 4; i++) {
            v[i] = rp[lane + 32 * i];
            ss += v[i].x*v[i].x + v[i].y*v[i].y + v[i].z*v[i].z + v[i].w*v[i].w;
        }
#pragma unroll
        for (int o = 16; o; o >>= 1) ss += __shfl_xor_sync(0xffffffffu, ss, o);
        float inv = 1.0f / fmaxf(sqrtf(ss), 1e-8f);
#pragma unroll
        for (int i = 0; i < 4; i++) {
            int c = 4 * (lane + 32 * i);
            sx[row][c]     = v[i].x * inv;
            sx[row][c + 1] = v[i].y * inv;
            sx[row][c + 2] = v[i].z * inv;
            sx[row][c + 3] = v[i].w * inv;
        }
    }
    __syncthreads();
    // write transposed: each warp 64 d's, two per iter (16 lanes each)
    int m = lane & 15, hw = lane >> 4;
#pragma unroll
    for (int dd = 0; dd < 32; dd++) {
        int d = w * 64 + dd * 2 + hw;
        g_cT[(size_t)d * MAXK + k0 + m] = sx[m][d];
    }
}

// ---------------------------------------------------------------------------
// Kernel 2: x = 0.5*st/||st|| + 0.5*ad/||ad||, write TRANSPOSED g_xT[d][m]
// ---------------------------------------------------------------------------
__global__ __launch_bounds__(256) void combine_T(const float* __restrict__ st,
                                                 const float* __restrict__ ad) {
    __shared__ float sx[16][529];
    int t = threadIdx.x, lane = t & 31, w = t >> 5;
    int m0 = blockIdx.x * 16;
#pragma unroll
    for (int rr = 0; rr < 2; rr++) {
        int row = w * 2 + rr;
        const float4* sp = (const float4*)(st + (size_t)(m0 + row) * D_DIM);
        const float4* ap = (const float4*)(ad + (size_t)(m0 + row) * D_DIM);
        float4 sv[4], av[4]; float ss = 0.f, aa = 0.f;
#pragma unroll
        for (int i = 0; i < 4; i++) {
            sv[i] = sp[lane + 32 * i];
            av[i] = ap[lane + 32 * i];
            ss += sv[i].x*sv[i].x + sv[i].y*sv[i].y + sv[i].z*sv[i].z + sv[i].w*sv[i].w;
            aa += av[i].x*av[i].x + av[i].y*av[i].y + av[i].z*av[i].z + av[i].w*av[i].w;
        }
#pragma unroll
        for (int o = 16; o; o >>= 1) {
            ss += __shfl_xor_sync(0xffffffffu, ss, o);
            aa += __shfl_xor_sync(0xffffffffu, aa, o);
        }
        float is = 0.5f / fmaxf(sqrtf(ss), 1e-8f);
        float ia = 0.5f / fmaxf(sqrtf(aa), 1e-8f);
#pragma unroll
        for (int i = 0; i < 4; i++) {
            int c = 4 * (lane + 32 * i);
            sx[row][c]     = sv[i].x * is + av[i].x * ia;
            sx[row][c + 1] = sv[i].y * is + av[i].y * ia;
            sx[row][c + 2] = sv[i].z * is + av[i].z * ia;
            sx[row][c + 3] = sv[i].w * is + av[i].w * ia;
        }
    }
    __syncthreads();
    int m = lane & 15, hw = lane >> 4;
#pragma unroll
    for (int dd = 0; dd < 32; dd++) {
        int d = w * 64 + dd * 2 + hw;
        g_xT[(size_t)d * MAXN + m0 + m] = sx[m][d];
    }
}

// ---------------------------------------------------------------------------
// Kernel 3: FFMA2 GEMM (128x128 tile, BK=32, 256 thr, occ 1) with threefry
//   noise generation interleaved into the mainloop (alu pipe hides under fma).
//   Noise parked in smem: m1 = -log(u1) (argmax path), eg2 = -1/log(u2).
//   Epilogue: v1 = sim + (-log(m1)) -> argmax partials; p = exp(sim)*eg2 -> ws.
// SMEM floats: A stages [0,4096),[4096,8192); B [8192,12288),[12288,16384)
//              m1s [16384,32768); eg2s [32768,49152)   -> 192KB
// ---------------------------------------------------------------------------
DI void issue_chunk(int c, int s, uint32_t sbase, int bm, int bn, int t) {
#pragma unroll
    for (int i = 0; i < 4; i++) {
        int u = t + i * 256;
        int kk = u >> 5, j4 = (u & 31) << 2;
        const float* ga = g_xT + (size_t)(c * 32 + kk) * MAXN + bm + j4;
        cp16(sbase + (uint32_t)(s * 4096 + kk * 128 + j4) * 4u, ga);
        const float* gb = g_cT + (size_t)(c * 32 + kk) * MAXK + bn + j4;
        cp16(sbase + (uint32_t)(8192 + s * 4096 + kk * 128 + j4) * 4u, gb);
    }
}

__global__ __launch_bounds__(256, 1) void gemm_fused(
        float* __restrict__ ws,
        uint32_t k1a, uint32_t k1b, uint32_t k2a, uint32_t k2b) {
    extern __shared__ float sm[];
    const uint32_t sbase = smem_u32(sm);
    const int t = threadIdx.x, lane = t & 31;
    const int tx = t & 15, ty = t >> 4;
    const int bn = blockIdx.x * 128, bm = blockIdx.y * 128;

    u64 acc[8][4];
#pragma unroll
    for (int i = 0; i < 8; i++)
#pragma unroll
        for (int j = 0; j < 4; j++) acc[i][j] = 0ull;

    issue_chunk(0, 0, sbase, bm, bn, t);
    CP_COMMIT();

    for (int c = 0; c < 16; c++) {
        if (c < 15) {
            issue_chunk(c + 1, (c + 1) & 1, sbase, bm, bn, t);
            CP_COMMIT();
            CP_WAIT1();
        } else {
            CP_WAIT0();
        }
        __syncthreads();
        const uint32_t AS = sbase + (uint32_t)((c & 1) * 4096) * 4u;
        const uint32_t BS = sbase + (uint32_t)(8192 + (c & 1) * 4096) * 4u;
#pragma unroll 1
        for (int g = 0; g < 4; g++) {
#pragma unroll
            for (int k8 = 0; k8 < 8; k8++) {
                int kk = g * 8 + k8;
                float a[8], b[8];
                lds128(a,     AS + (uint32_t)(kk * 128 + ty * 8) * 4u);
                lds128(a + 4, AS + (uint32_t)(kk * 128 + ty * 8) * 4u + 16u);
                lds128(b,     BS + (uint32_t)(kk * 128 + tx * 8) * 4u);
                lds128(b + 4, BS + (uint32_t)(kk * 128 + tx * 8) * 4u + 16u);
                u64 b2[4];
#pragma unroll
                for (int j = 0; j < 4; j++) b2[j] = pk2(b[2 * j], b[2 * j + 1]);
#pragma unroll
                for (int i = 0; i < 8; i++) {
                    u64 a2 = pk2(a[i], a[i]);
#pragma unroll
                    for (int j = 0; j < 4; j++)
                        acc[i][j] = fma2(a2, b2[j], acc[i][j]);
                }
            }
            // interleaved noise for element e = c*4 + g (alu pipe, hides under fma)
            {
                int e = c * 4 + g;
                int i = e >> 3, ci = e & 7;
                uint32_t ctr = (uint32_t)(bm + ty * 8 + i) * 1024u
                             + (uint32_t)(bn + tx * 8 + ci);
                uint32_t b1 = tf_bits(k1a, k1b, ctr);
                float u1 = __uint_as_float((b1 >> 9) | 0x3f800000u) - 1.0f;
                float m1 = -__nv_logf(fmaxf(TINYF, u1 + TINYF));
                sm[16384 + e * 256 + t] = m1;
                uint32_t bb = tf_bits(k2a, k2b, ctr);
                float u2 = __uint_as_float((bb >> 9) | 0x3f800000u) - 1.0f;
                float eg = -__fdividef(1.0f, __nv_logf(fmaxf(TINYF, u2 + TINYF)));
                sm[32768 + e * 256 + t] = eg;
            }
        }
        __syncthreads();
    }

    // ---- epilogue: cheap (noise precomputed) ----
#pragma unroll 1
    for (int i = 0; i < 8; i++) {
        float o[8];
#pragma unroll
        for (int j = 0; j < 4; j++) upk2(acc[i][j], o[2 * j], o[2 * j + 1]);
        int grow = bm + ty * 8 + i;
        float bmax = -3.4e38f; int bidx = 0; float bsum = 0.f;
        float p[8];
#pragma unroll
        for (int ci = 0; ci < 8; ci++) {
            int e = i * 8 + ci;
            float m1 = sm[16384 + e * 256 + t];
            float v1 = o[ci] - __nv_logf(m1);
            int gcol = bn + tx * 8 + ci;
            if (v1 > bmax) { bmax = v1; bidx = gcol; }
            float eg = sm[32768 + e * 256 + t];
            p[ci] = __expf(o[ci]) * eg;
            bsum += p[ci];
        }
        float* wrow = ws + (size_t)grow * 1024 + bn + tx * 8;
        *(float4*)(wrow)     = make_float4(p[0], p[1], p[2], p[3]);
        *(float4*)(wrow + 4) = make_float4(p[4], p[5], p[6], p[7]);
        // reduce across the 16 tx lanes (half-warp)
#pragma unroll
        for (int off = 8; off; off >>= 1) {
            float om = __shfl_xor_sync(0xffffffffu, bmax, off);
            int   oi = __shfl_xor_sync(0xffffffffu, bidx, off);
            float os = __shfl_xor_sync(0xffffffffu, bsum, off);
            if (om > bmax || (om == bmax && oi < bidx)) { bmax = om; bidx = oi; }
            bsum += os;
        }
        if ((lane & 15) == 0) {
            size_t pidx = (size_t)grow * NBN + blockIdx.x;
            g_pm[pidx] = bmax; g_pi[pidx] = bidx; g_ps[pidx] = bsum;
        }
    }
}

// ---------------------------------------------------------------------------
// Kernel 4: reduce partials per row, normalize ws, gather z_q, indices.
// ---------------------------------------------------------------------------
__global__ void finalize_kernel(const float* __restrict__ cb,
                                float* __restrict__ zq,
                                float* __restrict__ ws,
                                float* __restrict__ idxo) {
    int n = blockIdx.x, t = threadIdx.x;
    __shared__ int   s_best;
    __shared__ float s_inv;
    if (t == 0) {
        float bm = g_pm[(size_t)n * NBN]; int bi = g_pi[(size_t)n * NBN];
        float sum = g_ps[(size_t)n * NBN];
#pragma unroll
        for (int j = 1; j < NBN; j++) {
            float m = g_pm[(size_t)n * NBN + j];
            int   i = g_pi[(size_t)n * NBN + j];
            if (m > bm || (m == bm && i < bi)) { bm = m; bi = i; }
            sum += g_ps[(size_t)n * NBN + j];
        }
        s_best = bi;
        s_inv  = 1.0f / sum;
    }
    __syncthreads();
    int best = s_best; float inv = s_inv;

    float4* wrow = (float4*)(ws + (size_t)n * 1024);
    float4 v = wrow[t];
    v.x *= inv; v.y *= inv; v.z *= inv; v.w *= inv;
    wrow[t] = v;

    if (t < 128) {
        float4 c = *(const float4*)(cb + (size_t)best * D_DIM + t * 4);
        *(float4*)(zq + (size_t)n * D_DIM + t * 4) = c;
    }
    if (t == 0) idxo[n] = (float)best;
}

// ---------------------------------------------------------------------------
extern "C" void kernel_launch(void* const* d_in, const int* in_sizes, int n_in,
                              void* d_out, int out_size) {
    const float* st = (const float*)d_in[0];
    const float* ad = (const float*)d_in[1];
    const float* cb = (const float*)d_in[2];
    int N = in_sizes[0] / D_DIM;     // 32768
    int K = in_sizes[2] / D_DIM;     // 1024

    float* out  = (float*)d_out;
    float* zq   = out;                              // [N, D]
    float* ws   = out + (size_t)N * D_DIM;          // [N, K]
    float* idxo = ws + (size_t)N * K;               // [N, 1]

    // jax.random.key(42) -> (0,42); partitionable fold split
    uint32_t g1a = 0u, g1b = 0u;
    threefry2x32(0u, 42u, g1a, g1b);    // counter 0 -> gk1
    uint32_t g2a = 0u, g2b = 1u;
    threefry2x32(0u, 42u, g2a, g2b);    // counter 1 -> gk2

    static int smem_set = 0;
    if (!smem_set) {
        cudaFuncSetAttribute(gemm_fused,
            cudaFuncAttributeMaxDynamicSharedMemorySize, 49152 * 4);
        smem_set = 1;
    }

    norm_cb_T<<<K / 16, 256>>>(cb);
    combine_T<<<N / 16, 256>>>(st, ad);
    dim3 gg(K / 128, N / 128);
    gemm_fused<<<gg, 256, 49152 * 4>>>(ws, g1a, g1b, g2a, g2b);
    finalize_kernel<<<N, 256>>>(cb, zq, ws, idxo);
}

// round 7
// speedup vs baseline: 1.2639x; 1.2639x over previous
#include <cuda_runtime.h>
#include <cstdint>
#include <cstddef>

#define DI __device__ __forceinline__
static const int D_DIM = 512;
#define MAXN 32768
#define MAXK 1024
#define NBN  8

extern "C" __device__ float __nv_logf(float);

// Scratch (device globals; no allocation allowed)
__device__ float g_xT[(size_t)D_DIM * MAXN];   // 64MB transposed combined input [d][m]
__device__ float g_cT[(size_t)D_DIM * MAXK];   //  2MB transposed normalized codebook [d][k]
__device__ float g_pm[(size_t)MAXN * NBN];
__device__ int   g_pi[(size_t)MAXN * NBN];
__device__ float g_ps[(size_t)MAXN * NBN];

// ---------------------------------------------------------------------------
// Threefry-2x32 (exact JAX, partitionable mode)
// ---------------------------------------------------------------------------
__host__ __device__ inline uint32_t rotl32(uint32_t x, int r) {
    return (x << r) | (x >> (32 - r));
}
__host__ __device__ inline void threefry2x32(uint32_t k0, uint32_t k1,
                                             uint32_t& x0, uint32_t& x1) {
    uint32_t k2 = k0 ^ k1 ^ 0x1BD11BDAu;
    x0 += k0; x1 += k1;
#define TFR(r) { x0 += x1; x1 = rotl32(x1, r); x1 ^= x0; }
    TFR(13) TFR(15) TFR(26) TFR(6)
    x0 += k1; x1 += k2 + 1u;
    TFR(17) TFR(29) TFR(16) TFR(24)
    x0 += k2; x1 += k0 + 2u;
    TFR(13) TFR(15) TFR(26) TFR(6)
    x0 += k0; x1 += k1 + 3u;
    TFR(17) TFR(29) TFR(16) TFR(24)
    x0 += k1; x1 += k2 + 4u;
    TFR(13) TFR(15) TFR(26) TFR(6)
    x0 += k2; x1 += k0 + 5u;
#undef TFR
}
DI uint32_t tf_bits(uint32_t k0, uint32_t k1, uint32_t i) {
    uint32_t x0 = 0u, x1 = i;
    threefry2x32(k0, k1, x0, x1);
    return x0 ^ x1;
}
#define TINYF 1.17549435e-38f

// ---------------------------------------------------------------------------
// Packed fp32x2 FMA + misc helpers
// ---------------------------------------------------------------------------
typedef unsigned long long u64;
DI u64 pk2(float lo, float hi) {
    u64 r; asm("mov.b64 %0, {%1,%2};" : "=l"(r) : "f"(lo), "f"(hi)); return r;
}
DI void upk2(u64 p, float& lo, float& hi) {
    asm("mov.b64 {%0,%1}, %2;" : "=f"(lo), "=f"(hi) : "l"(p));
}
DI u64 fma2(u64 a, u64 b, u64 c) {
    u64 d; asm("fma.rn.f32x2 %0, %1, %2, %3;" : "=l"(d) : "l"(a), "l"(b), "l"(c));
    return d;
}
DI uint32_t smem_u32(const void* p) {
    uint32_t a;
    asm("{ .reg .u64 t; cvta.to.shared.u64 t, %1; cvt.u32.u64 %0, t; }"
        : "=r"(a) : "l"(p));
    return a;
}
DI void cp16(uint32_t saddr, const void* g) {
    asm volatile("cp.async.cg.shared.global [%0], [%1], 16;"
                 :: "r"(saddr), "l"(g) : "memory");
}
#define CP_COMMIT() asm volatile("cp.async.commit_group;" ::: "memory")
#define CP_WAIT1()  asm volatile("cp.async.wait_group 1;" ::: "memory")
#define CP_WAIT0()  asm volatile("cp.async.wait_group 0;" ::: "memory")
DI void lds128(float* r, uint32_t addr) {
    asm volatile("ld.shared.v4.f32 {%0,%1,%2,%3}, [%4];"
        : "=f"(r[0]), "=f"(r[1]), "=f"(r[2]), "=f"(r[3]) : "r"(addr));
}
DI void barx(int id, int n) {
    asm volatile("bar.sync %0, %1;" :: "r"(id), "r"(n) : "memory");
}

// ---------------------------------------------------------------------------
// Kernel 1: codebook: normalize rows, write TRANSPOSED g_cT[d][k]
// ---------------------------------------------------------------------------
__global__ __launch_bounds__(256) void norm_cb_T(const float* __restrict__ cb) {
    __shared__ float sx[16][529];
    int t = threadIdx.x, lane = t & 31, w = t >> 5;
    int k0 = blockIdx.x * 16;
#pragma unroll
    for (int rr = 0; rr < 2; rr++) {
        int row = w * 2 + rr;
        const float4* rp = (const float4*)(cb + (size_t)(k0 + row) * D_DIM);
        float4 v[4]; float ss = 0.f;
#pragma unroll
        for (int i = 0; i < 4; i++) {
            v[i] = rp[lane + 32 * i];
            ss += v[i].x*v[i].x + v[i].y*v[i].y + v[i].z*v[i].z + v[i].w*v[i].w;
        }
#pragma unroll
        for (int o = 16; o; o >>= 1) ss += __shfl_xor_sync(0xffffffffu, ss, o);
        float inv = 1.0f / fmaxf(sqrtf(ss), 1e-8f);
#pragma unroll
        for (int i = 0; i < 4; i++) {
            int c = 4 * (lane + 32 * i);
            sx[row][c]     = v[i].x * inv;
            sx[row][c + 1] = v[i].y * inv;
            sx[row][c + 2] = v[i].z * inv;
            sx[row][c + 3] = v[i].w * inv;
        }
    }
    __syncthreads();
    int m = lane & 15, hw = lane >> 4;
#pragma unroll
    for (int dd = 0; dd < 32; dd++) {
        int d = w * 64 + dd * 2 + hw;
        g_cT[(size_t)d * MAXK + k0 + m] = sx[m][d];
    }
}

// ---------------------------------------------------------------------------
// Kernel 2: x = 0.5*st/||st|| + 0.5*ad/||ad||, write TRANSPOSED g_xT[d][m]
// ---------------------------------------------------------------------------
__global__ __launch_bounds__(256) void combine_T(const float* __restrict__ st,
                                                 const float* __restrict__ ad) {
    __shared__ float sx[16][529];
    int t = threadIdx.x, lane = t & 31, w = t >> 5;
    int m0 = blockIdx.x * 16;
#pragma unroll
    for (int rr = 0; rr < 2; rr++) {
        int row = w * 2 + rr;
        const float4* sp = (const float4*)(st + (size_t)(m0 + row) * D_DIM);
        const float4* ap = (const float4*)(ad + (size_t)(m0 + row) * D_DIM);
        float4 sv[4], av[4]; float ss = 0.f, aa = 0.f;
#pragma unroll
        for (int i = 0; i < 4; i++) {
            sv[i] = sp[lane + 32 * i];
            av[i] = ap[lane + 32 * i];
            ss += sv[i].x*sv[i].x + sv[i].y*sv[i].y + sv[i].z*sv[i].z + sv[i].w*sv[i].w;
            aa += av[i].x*av[i].x + av[i].y*av[i].y + av[i].z*av[i].z + av[i].w*av[i].w;
        }
#pragma unroll
        for (int o = 16; o; o >>= 1) {
            ss += __shfl_xor_sync(0xffffffffu, ss, o);
            aa += __shfl_xor_sync(0xffffffffu, aa, o);
        }
        float is = 0.5f / fmaxf(sqrtf(ss), 1e-8f);
        float ia = 0.5f / fmaxf(sqrtf(aa), 1e-8f);
#pragma unroll
        for (int i = 0; i < 4; i++) {
            int c = 4 * (lane + 32 * i);
            sx[row][c]     = sv[i].x * is + av[i].x * ia;
            sx[row][c + 1] = sv[i].y * is + av[i].y * ia;
            sx[row][c + 2] = sv[i].z * is + av[i].z * ia;
            sx[row][c + 3] = sv[i].w * is + av[i].w * ia;
        }
    }
    __syncthreads();
    int m = lane & 15, hw = lane >> 4;
#pragma unroll
    for (int dd = 0; dd < 32; dd++) {
        int d = w * 64 + dd * 2 + hw;
        g_xT[(size_t)d * MAXN + m0 + m] = sx[m][d];
    }
}

// ---------------------------------------------------------------------------
// Kernel 3: warp-specialized FFMA2 GEMM + threefry noise.
//   384 threads: t<256 GEMM (128x128 tile, BK=32, double-buffered cp.async,
//   named barrier 1), t>=256 noise (4 warps, threefry -> smem float2, no
//   mainloop barriers). Join at __syncthreads, then light epilogue.
// SMEM floats: A [0,8192) 2 stages; B [8192,16384) 2 stages;
//              noise float2[16384] at +16384 floats. Total 192KB.
// ---------------------------------------------------------------------------
DI void issue_chunk(int c, int s, uint32_t sbase, int bm, int bn, int t) {
#pragma unroll
    for (int i = 0; i < 4; i++) {
        int u = t + i * 256;
        int kk = u >> 5, j4 = (u & 31) << 2;
        const float* ga = g_xT + (size_t)(c * 32 + kk) * MAXN + bm + j4;
        cp16(sbase + (uint32_t)(s * 4096 + kk * 128 + j4) * 4u, ga);
        const float* gb = g_cT + (size_t)(c * 32 + kk) * MAXK + bn + j4;
        cp16(sbase + (uint32_t)(8192 + s * 4096 + kk * 128 + j4) * 4u, gb);
    }
}

__global__ __launch_bounds__(384, 1) void gemm_ws(
        float* __restrict__ ws,
        uint32_t k1a, uint32_t k1b, uint32_t k2a, uint32_t k2b) {
    extern __shared__ float sm[];
    const uint32_t sbase = smem_u32(sm);
    float2* nz = (float2*)(sm + 16384);
    const int t = threadIdx.x;
    const int bn = blockIdx.x * 128, bm = blockIdx.y * 128;

    if (t < 256) {
        // ===================== GEMM role =====================
        const int lane = t & 31;
        const int tx = t & 15, ty = t >> 4;

        u64 acc[8][4];
#pragma unroll
        for (int i = 0; i < 8; i++)
#pragma unroll
            for (int j = 0; j < 4; j++) acc[i][j] = 0ull;

        issue_chunk(0, 0, sbase, bm, bn, t);
        CP_COMMIT();

        for (int c = 0; c < 16; c++) {
            if (c < 15) {
                issue_chunk(c + 1, (c + 1) & 1, sbase, bm, bn, t);
                CP_COMMIT();
                CP_WAIT1();
            } else {
                CP_WAIT0();
            }
            barx(1, 256);
            const uint32_t AS = sbase + (uint32_t)((c & 1) * 4096) * 4u;
            const uint32_t BS = sbase + (uint32_t)(8192 + (c & 1) * 4096) * 4u;
#pragma unroll
            for (int kk = 0; kk < 32; kk++) {
                float a[8], b[8];
                lds128(a,     AS + (uint32_t)(kk * 128 + ty * 8) * 4u);
                lds128(a + 4, AS + (uint32_t)(kk * 128 + ty * 8) * 4u + 16u);
                lds128(b,     BS + (uint32_t)(kk * 128 + tx * 8) * 4u);
                lds128(b + 4, BS + (uint32_t)(kk * 128 + tx * 8) * 4u + 16u);
                u64 b2[4];
#pragma unroll
                for (int j = 0; j < 4; j++) b2[j] = pk2(b[2 * j], b[2 * j + 1]);
#pragma unroll
                for (int i = 0; i < 8; i++) {
                    u64 a2 = pk2(a[i], a[i]);
#pragma unroll
                    for (int j = 0; j < 4; j++)
                        acc[i][j] = fma2(a2, b2[j], acc[i][j]);
                }
            }
            barx(1, 256);
        }

        __syncthreads();   // join with noise warps (drains their STS)

        // ---- epilogue: noise precomputed in smem ----
#pragma unroll 1
        for (int i = 0; i < 8; i++) {
            float o[8];
#pragma unroll
            for (int j = 0; j < 4; j++) upk2(acc[i][j], o[2 * j], o[2 * j + 1]);
            int grow = bm + ty * 8 + i;
            float bmax = -3.4e38f; int bidx = 0; float bsum = 0.f;
            float p[8];
#pragma unroll
            for (int ci = 0; ci < 8; ci++) {
                float2 nv = nz[(i * 8 + ci) * 256 + t];
                float v1 = o[ci] - __nv_logf(nv.x);
                int gcol = bn + tx * 8 + ci;
                if (v1 > bmax) { bmax = v1; bidx = gcol; }
                p[ci] = __expf(o[ci]) * nv.y;
                bsum += p[ci];
            }
            float* wrow = ws + (size_t)grow * 1024 + bn + tx * 8;
            *(float4*)(wrow)     = make_float4(p[0], p[1], p[2], p[3]);
            *(float4*)(wrow + 4) = make_float4(p[4], p[5], p[6], p[7]);
#pragma unroll
            for (int off = 8; off; off >>= 1) {
                float om = __shfl_xor_sync(0xffffffffu, bmax, off);
                int   oi = __shfl_xor_sync(0xffffffffu, bidx, off);
                float os = __shfl_xor_sync(0xffffffffu, bsum, off);
                if (om > bmax || (om == bmax && oi < bidx)) { bmax = om; bidx = oi; }
                bsum += os;
            }
            if ((lane & 15) == 0) {
                size_t pidx = (size_t)grow * NBN + blockIdx.x;
                g_pm[pidx] = bmax; g_pi[pidx] = bidx; g_ps[pidx] = bsum;
            }
        }
    } else {
        // ===================== noise role =====================
        const int j = t - 256;   // 0..127
#pragma unroll 1
        for (int it = 0; it < 128; it++) {
            int idx = it * 128 + j;
            int tt = idx & 255, e = idx >> 8;
            int i = e >> 3, ci = e & 7;
            int tty = tt >> 4, ttx = tt & 15;
            uint32_t ctr = (uint32_t)(bm + tty * 8 + i) * 1024u
                         + (uint32_t)(bn + ttx * 8 + ci);
            uint32_t b1 = tf_bits(k1a, k1b, ctr);
            float u1 = __uint_as_float((b1 >> 9) | 0x3f800000u) - 1.0f;
            float m1 = -__nv_logf(fmaxf(TINYF, u1 + TINYF));
            uint32_t b2 = tf_bits(k2a, k2b, ctr);
            float u2 = __uint_as_float((b2 >> 9) | 0x3f800000u) - 1.0f;
            float eg = -__fdividef(1.0f, __nv_logf(fmaxf(TINYF, u2 + TINYF)));
            nz[idx] = make_float2(m1, eg);
        }
        __syncthreads();   // join; GEMM warps do the epilogue
    }
}

// ---------------------------------------------------------------------------
// Kernel 4: reduce partials per row, normalize ws, gather z_q, indices.
// ---------------------------------------------------------------------------
__global__ void finalize_kernel(const float* __restrict__ cb,
                                float* __restrict__ zq,
                                float* __restrict__ ws,
                                float* __restrict__ idxo) {
    int n = blockIdx.x, t = threadIdx.x;
    __shared__ int   s_best;
    __shared__ float s_inv;
    if (t == 0) {
        float bm = g_pm[(size_t)n * NBN]; int bi = g_pi[(size_t)n * NBN];
        float sum = g_ps[(size_t)n * NBN];
#pragma unroll
        for (int j = 1; j < NBN; j++) {
            float m = g_pm[(size_t)n * NBN + j];
            int   i = g_pi[(size_t)n * NBN + j];
            if (m > bm || (m == bm && i < bi)) { bm = m; bi = i; }
            sum += g_ps[(size_t)n * NBN + j];
        }
        s_best = bi;
        s_inv  = 1.0f / sum;
    }
    __syncthreads();
    int best = s_best; float inv = s_inv;

    float4* wrow = (float4*)(ws + (size_t)n * 1024);
    float4 v = wrow[t];
    v.x *= inv; v.y *= inv; v.z *= inv; v.w *= inv;
    wrow[t] = v;

    if (t < 128) {
        float4 c = *(const float4*)(cb + (size_t)best * D_DIM + t * 4);
        *(float4*)(zq + (size_t)n * D_DIM + t * 4) = c;
    }
    if (t == 0) idxo[n] = (float)best;
}

// ---------------------------------------------------------------------------
extern "C" void kernel_launch(void* const* d_in, const int* in_sizes, int n_in,
                              void* d_out, int out_size) {
    const float* st = (const float*)d_in[0];
    const float* ad = (const float*)d_in[1];
    const float* cb = (const float*)d_in[2];
    int N = in_sizes[0] / D_DIM;     // 32768
    int K = in_sizes[2] / D_DIM;     // 1024

    float* out  = (float*)d_out;
    float* zq   = out;                              // [N, D]
    float* ws   = out + (size_t)N * D_DIM;          // [N, K]
    float* idxo = ws + (size_t)N * K;               // [N, 1]

    // jax.random.key(42) -> (0,42); partitionable fold split
    uint32_t g1a = 0u, g1b = 0u;
    threefry2x32(0u, 42u, g1a, g1b);    // counter 0 -> gk1
    uint32_t g2a = 0u, g2b = 1u;
    threefry2x32(0u, 42u, g2a, g2b);    // counter 1 -> gk2

    cudaFuncSetAttribute(gemm_ws,
        cudaFuncAttributeMaxDynamicSharedMemorySize, 49152 * 4);

    norm_cb_T<<<K / 16, 256>>>(cb);
    combine_T<<<N / 16, 256>>>(st, ad);
    dim3 gg(K / 128, N / 128);
    gemm_ws<<<gg, 384, 49152 * 4>>>(ws, g1a, g1b, g2a, g2b);
    finalize_kernel<<<N, 256>>>(cb, zq, ws, idxo);
}